// round 5
// baseline (speedup 1.0000x reference)
#include <cuda_runtime.h>
#include <cstdint>

// Shapes (fixed)
#define N_TOTAL 2048
#define T_DIM   128
#define F_DIM   32
#define K_DIM   32

#define NB      16                 // n per block
#define TC      8                  // t per chunk
#define CHUNKS  (T_DIM / TC)       // 16
#define PAIRS   (CHUNKS / 2)       // 8 (two teams, one chunk each per pair)
#define THREADS 512                // 16 warps = 2 teams x 8 warps
#define NBLOCKS (N_TOTAL / NB)     // 128

#define XBUF_FLOATS (NB * TC * F_DIM)      // 4096  (16KB per slot)
#define CBUF_FLOATS (K_DIM * TC * F_DIM)   // 8192  (32KB per slot)
#define NSLOTS      4
#define SMEM_FLOATS (NSLOTS * (XBUF_FLOATS + CBUF_FLOATS))   // 49152
#define SMEM_BYTES  (SMEM_FLOATS * 4)                        // 192KB

typedef unsigned long long u64;

__device__ __forceinline__ void cp_async16(uint32_t dst, const void* src) {
    asm volatile("cp.async.cg.shared.global [%0], [%1], 16;\n" :: "r"(dst), "l"(src));
}
__device__ __forceinline__ void cp_commit() {
    asm volatile("cp.async.commit_group;\n" ::: "memory");
}
__device__ __forceinline__ void cp_wait1() {
    asm volatile("cp.async.wait_group 1;\n" ::: "memory");
}
__device__ __forceinline__ void ffma2(u64& d, u64 a, u64 b, u64 c) {
    asm("fma.rn.f32x2 %0, %1, %2, %3;" : "=l"(d) : "l"(a), "l"(b), "l"(c));
}
__device__ __forceinline__ u64 fadd2(u64 a, u64 b) {
    u64 d; asm("add.rn.f32x2 %0, %1, %2;" : "=l"(d) : "l"(a), "l"(b)); return d;
}
__device__ __forceinline__ float fsqrt_approx(float v) {
    float r; asm("sqrt.approx.f32 %0, %1;" : "=f"(r) : "f"(v)); return r;
}
__device__ __forceinline__ float frcp_approx(float v) {
    float r; asm("rcp.approx.f32 %0, %1;" : "=f"(r) : "f"(v)); return r;
}
__device__ __forceinline__ u64 lds64(const float* p) {
    return *reinterpret_cast<const u64*>(p);
}
__device__ __forceinline__ float lo32(u64 v) { return __uint_as_float((unsigned)v); }
__device__ __forceinline__ float hi32(u64 v) { return __uint_as_float((unsigned)(v >> 32)); }

#define NEG2_PACKED 0xC0000000C0000000ULL

extern "C" __global__ void __launch_bounds__(THREADS, 1)
ts_clustering_kernel(const float* __restrict__ x,
                     const float* __restrict__ clusters,
                     float* __restrict__ out) {
    extern __shared__ float smem[];
    const uint32_t smem_u32 = (uint32_t)__cvta_generic_to_shared(smem);

    const int tid  = threadIdx.x;
    const int lane = tid & 31;
    const int w    = tid >> 5;          // 0..15
    const int team = w >> 3;            // 0..1  (t-split teams)
    const int wt   = w & 7;             // warp within team
    const int wn   = wt & 1;            // n-group (8 n each)
    const int wk   = wt >> 1;           // k-group (8 k each)
    const int fp   = lane & 15;         // f-pair 0..15
    const int nsub = lane >> 4;         // n-half
    const int nBase = blockIdx.x * NB;

    const int base_n = wn * 8 + nsub * 4;   // 4 n's per lane
    const int base_k = wk * 8;              // 8 k's per warp

    // ---- prefetch one chunk into slot (ci & 3) -------------------------------
    auto prefetch = [&](int ci) {
        const int t0 = ci * TC;
        const int s  = ci & 3;
        const uint32_t xs_b = smem_u32 + (uint32_t)s * (XBUF_FLOATS * 4);
        #pragma unroll
        for (int r = 0; r < 2; r++) {                 // x: 1024 x 16B
            int idx = tid + r * THREADS;
            int n   = idx >> 6;
            int rem = idx & 63;
            const char* src = (const char*)x
                + ((size_t)(nBase + n) * T_DIM + t0) * (F_DIM * 4) + (size_t)rem * 16;
            cp_async16(xs_b + (uint32_t)idx * 16, src);
        }
        const uint32_t cs_b = smem_u32 + (uint32_t)(NSLOTS * XBUF_FLOATS * 4)
                            + (uint32_t)s * (CBUF_FLOATS * 4);
        #pragma unroll
        for (int r = 0; r < 4; r++) {                 // c: 2048 x 16B
            int idx = tid + r * THREADS;
            int k   = idx >> 6;
            int rem = idx & 63;
            const char* src = (const char*)clusters
                + ((size_t)k * T_DIM + t0) * (F_DIM * 4) + (size_t)rem * 16;
            cp_async16(cs_b + (uint32_t)idx * 16, src);
        }
    };

    // ---- per-team accumulators (packed f32x2 over the f-pair) ----------------
    u64 acc[4][8];
    #pragma unroll
    for (int i = 0; i < 4; i++)
        #pragma unroll
        for (int j = 0; j < 8; j++) acc[i][j] = 0ULL;
    u64 sx2p[4] = {0ULL, 0ULL, 0ULL, 0ULL};   // x^2 for 4 n's, t-phase (t&3)==wk
    u64 sc2p[4] = {0ULL, 0ULL, 0ULL, 0ULL};   // c^2 for 4 k's (nsub half), (t&1)==wn

    prefetch(0); prefetch(1);
    cp_commit();

    for (int p = 0; p < PAIRS; p++) {
        if (p + 1 < PAIRS) { prefetch(2 * p + 2); prefetch(2 * p + 3); }
        cp_commit();            // uniform group count
        cp_wait1();             // pair p resident
        __syncthreads();

        const int ci = 2 * p + team;
        const int s  = ci & 3;
        const float* xs = smem + s * XBUF_FLOATS;                       // [NB][TC][F]
        const float* cs = smem + NSLOTS * XBUF_FLOATS + s * CBUF_FLOATS; // [K][TC][F]
        const float* xp = xs + (base_n * TC) * F_DIM + 2 * fp;
        const float* cp = cs + (base_k * TC) * F_DIM + 2 * fp;

        #pragma unroll
        for (int t = 0; t < TC; t++) {
            u64 xr[4], cr[8];
            #pragma unroll
            for (int i = 0; i < 4; i++)
                xr[i] = lds64(xp + (i * TC + t) * F_DIM);
            #pragma unroll
            for (int j = 0; j < 8; j++)
                cr[j] = lds64(cp + (j * TC + t) * F_DIM);
            #pragma unroll
            for (int i = 0; i < 4; i++)
                #pragma unroll
                for (int j = 0; j < 8; j++)
                    ffma2(acc[i][j], xr[i], cr[j], acc[i][j]);
            if ((t & 3) == wk) {
                #pragma unroll
                for (int i = 0; i < 4; i++) ffma2(sx2p[i], xr[i], xr[i], sx2p[i]);
            }
            if ((t & 1) == wn) {                 // this lane owns k's [base_k+4*nsub, +4)
                #pragma unroll
                for (int j = 0; j < 4; j++)
                    ffma2(sc2p[j], cr[nsub * 4 + j], cr[nsub * 4 + j], sc2p[j]);
            }
        }
        __syncthreads();
    }

    // ---- epilogue ------------------------------------------------------------
    // smem reuse: accT1   floats [0, 16384)          team1 acc (u64 x 8192)
    //             x2part  floats [16384, 20480)      [2 tm][4 wk][16 n][16 fp] pairs
    //             c2part  floats [20480, 24576)      [2 tm][2 wn][32 k][16 fp] pairs
    //             dsts    floats [24576, 25088)      [16 n][32 k]
    __syncthreads();
    u64*   accT1  = reinterpret_cast<u64*>(smem);
    float* x2part = smem + 16384;
    float* c2part = smem + 20480;
    float* dsts   = smem + 24576;

    if (team == 1) {
        #pragma unroll
        for (int i = 0; i < 4; i++)
            #pragma unroll
            for (int j = 0; j < 8; j++)
                accT1[((wt * 32 + lane) * 32) + i * 8 + j] = acc[i][j];
    }
    #pragma unroll
    for (int i = 0; i < 4; i++) {
        int n = base_n + i;
        *reinterpret_cast<u64*>(&x2part[2 * (((team * 4 + wk) * 16 + n) * 16 + fp)]) = sx2p[i];
    }
    #pragma unroll
    for (int j = 0; j < 4; j++) {
        int k = base_k + nsub * 4 + j;
        *reinterpret_cast<u64*>(&c2part[2 * (((team * 2 + wn) * 32 + k) * 16 + fp)]) = sc2p[j];
    }
    __syncthreads();

    if (team == 0) {
        // merge team1's xc accumulators
        #pragma unroll
        for (int i = 0; i < 4; i++)
            #pragma unroll
            for (int j = 0; j < 8; j++)
                acc[i][j] = fadd2(acc[i][j], accT1[((wt * 32 + lane) * 32) + i * 8 + j]);

        // c2 totals for this warp's 8 k's at this fp: sum over 2 tm x 2 wn
        u64 c2p[8];
        #pragma unroll
        for (int j = 0; j < 8; j++) {
            int k = base_k + j;
            u64 s0 = fadd2(lds64(&c2part[2 * ((0 * 32 + k) * 16 + fp)]),
                           lds64(&c2part[2 * ((1 * 32 + k) * 16 + fp)]));
            u64 s1 = fadd2(lds64(&c2part[2 * ((2 * 32 + k) * 16 + fp)]),
                           lds64(&c2part[2 * ((3 * 32 + k) * 16 + fp)]));
            c2p[j] = fadd2(s0, s1);
        }

        #pragma unroll
        for (int i = 0; i < 4; i++) {
            int n = base_n + i;
            u64 x2p = 0ULL;
            #pragma unroll
            for (int g = 0; g < 8; g++) {   // 2 tm x 4 wk partials
                u64 v = lds64(&x2part[2 * ((g * 16 + n) * 16 + fp)]);
                x2p = (g == 0) ? v : fadd2(x2p, v);
            }
            #pragma unroll
            for (int j = 0; j < 8; j++) {
                u64 s  = fadd2(x2p, c2p[j]);
                u64 sq;
                ffma2(sq, acc[i][j], NEG2_PACKED, s);   // x2 + c2 - 2*xc
                float ed = fsqrt_approx(fmaxf(lo32(sq), 0.0f))
                         + fsqrt_approx(fmaxf(hi32(sq), 0.0f));
                #pragma unroll
                for (int off = 8; off > 0; off >>= 1)   // reduce 16 f-pairs
                    ed += __shfl_xor_sync(0xffffffffu, ed, off);
                if (fp == 0 && nsub == (lane >> 4))     // lanes 0 and 16 write (distinct n)
                    dsts[n * K_DIM + (base_k + j)] = ed;
            }
        }
    }
    __syncthreads();

    // ---- Student-t + per-n normalization: warp w handles n = w ---------------
    {
        float d = dsts[w * K_DIM + lane];
        float q = frcp_approx(fmaf(d, d, 1.0f));        // alpha = 1
        float sum = q;
        #pragma unroll
        for (int off = 16; off > 0; off >>= 1)
            sum += __shfl_xor_sync(0xffffffffu, sum, off);
        out[(size_t)(nBase + w) * K_DIM + lane] = q * frcp_approx(sum);
    }
}

extern "C" void kernel_launch(void* const* d_in, const int* in_sizes, int n_in,
                              void* d_out, int out_size) {
    const float* x        = (const float*)d_in[0];   // (2048, 128, 32)
    const float* clusters = (const float*)d_in[1];   // (32, 128, 32)
    float* out            = (float*)d_out;           // (2048, 32)
    (void)in_sizes; (void)n_in; (void)out_size;

    cudaFuncSetAttribute(ts_clustering_kernel,
                         cudaFuncAttributeMaxDynamicSharedMemorySize, SMEM_BYTES);
    ts_clustering_kernel<<<NBLOCKS, THREADS, SMEM_BYTES>>>(x, clusters, out);
}